// round 5
// baseline (speedup 1.0000x reference)
#include <cuda_runtime.h>
#include <cuda_bf16.h>
#include <math.h>
#include <stdint.h>

// Problem constants (fixed by the reference)
#define BB 64
#define TT 512
#define FF 513
#define HH 50
#define G4 200          // 4*H
#define MROWS (BB*TT)   // 32768

// Scratch (static device globals — no allocation in kernel_launch)
__device__ float g_xg[MROWS * G4];   // (B*T, 200): xg = x@W_ih^T + b_ih
__device__ float g_hs[MROWS * HH];   // (B*T, 50):  hidden states

// ===========================================================================
// Warp-MMA helpers (sm_80-era PTX: compiles at compute_103, runs on tensor pipe)
// ===========================================================================
__device__ __forceinline__ uint32_t smem_u32(const void* p) {
    uint32_t a;
    asm("{ .reg .u64 t; cvta.to.shared.u64 t, %1; cvt.u32.u64 %0, t; }"
        : "=r"(a) : "l"(p));
    return a;
}

__device__ __forceinline__ void ldsm4(uint32_t* r, uint32_t a) {
    asm volatile("ldmatrix.sync.aligned.m8n8.x4.shared.b16 {%0,%1,%2,%3}, [%4];"
                 : "=r"(r[0]), "=r"(r[1]), "=r"(r[2]), "=r"(r[3]) : "r"(a));
}

__device__ __forceinline__ void mma16816(float* c, const uint32_t* a,
                                         const uint32_t* b) {
    asm volatile(
        "mma.sync.aligned.m16n8k16.row.col.f32.bf16.bf16.f32 "
        "{%0,%1,%2,%3}, {%4,%5,%6,%7}, {%8,%9}, {%0,%1,%2,%3};"
        : "+f"(c[0]), "+f"(c[1]), "+f"(c[2]), "+f"(c[3])
        : "r"(a[0]), "r"(a[1]), "r"(a[2]), "r"(a[3]), "r"(b[0]), "r"(b[1]));
}

// pack two fp32 into bf16x2 hi and residual-lo words
__device__ __forceinline__ void split2(float x0, float x1,
                                       uint32_t& hi, uint32_t& lo) {
    __nv_bfloat16 h0 = __float2bfloat16(x0);
    __nv_bfloat16 h1 = __float2bfloat16(x1);
    __nv_bfloat16 l0 = __float2bfloat16(x0 - __bfloat162float(h0));
    __nv_bfloat16 l1 = __float2bfloat16(x1 - __bfloat162float(h1));
    __nv_bfloat162 hv(h0, h1), lv(l0, l1);
    hi = *(uint32_t*)&hv;
    lo = *(uint32_t*)&lv;
}

// ===========================================================================
// NT GEMM with bias on tensor cores via fp32 -> bf16 hi/lo split.
//   C[m,n] = sum_k A[m,k] * B[n,k] + bias[n]
// Block tile 128x128, K chunk 32, DOUBLE-BUFFERED dynamic smem (82 KB).
// 8 warps: 2(m) x 4(n); warp tile 64x32.
// smem rows padded to 40 bf16 (80 B) -> conflict-free ldmatrix.
// M must be a multiple of 128 (true: 32768). N, K arbitrary (guarded).
// ===========================================================================
#define LDR 40                       // smem row stride in bf16 elems (80 B)
#define MAT_ELEMS (128 * LDR)        // one matrix-half: 5120 bf16
#define MAT_BYTES (MAT_ELEMS * 2)    // 10240 B
#define STAGE_BYTES (4 * MAT_BYTES)  // Ahi|Alo|Bhi|Blo = 40960 B
#define SMEM_TOTAL (2 * STAGE_BYTES) // 81920 B

__global__ __launch_bounds__(256) void gemm_mma_nt(
    const float* __restrict__ A, const float* __restrict__ Bm,
    const float* __restrict__ bias, float* __restrict__ C,
    int M, int N, int K)
{
    extern __shared__ __align__(16) char smem[];
    const uint32_t sbase = smem_u32(smem);

    const int tid  = threadIdx.x;
    const int lane = tid & 31;
    const int wid  = tid >> 5;
    const int wm   = wid & 1;    // 0..1 -> m offset 0/64
    const int wn   = wid >> 1;   // 0..3 -> n offset 0/32/64/96

    const int m0 = blockIdx.x * 128;
    const int n0 = blockIdx.y * 128;

    float acc[4][4][4];
#pragma unroll
    for (int i = 0; i < 4; ++i)
#pragma unroll
        for (int j = 0; j < 4; ++j)
#pragma unroll
            for (int q = 0; q < 4; ++q) acc[i][j][q] = 0.f;

    // loader indexing: thread handles col pair (lc, lc+1), rows lr + 16*i
    const int lc = (tid & 15) * 2;
    const int lr = tid >> 4;

    const int nKC = (K + 31) / 32;

    uint32_t pah[8], pal[8], pbh[8], pbl[8];

    // ---- helper lambdas (inlined by compiler)
    auto prefetch = [&](int kc) {
        const int gk = kc * 32 + lc;
        const bool k0ok = (gk < K);
        const bool k1ok = (gk + 1 < K);
#pragma unroll
        for (int i = 0; i < 8; ++i) {
            const int row = lr + i * 16;
            float a0 = k0ok ? A[(size_t)(m0 + row) * K + gk] : 0.f;
            float a1 = k1ok ? A[(size_t)(m0 + row) * K + gk + 1] : 0.f;
            split2(a0, a1, pah[i], pal[i]);
            const int gn = n0 + row;
            const bool nok = (gn < N);
            float b0 = (k0ok && nok) ? Bm[(size_t)gn * K + gk] : 0.f;
            float b1 = (k1ok && nok) ? Bm[(size_t)gn * K + gk + 1] : 0.f;
            split2(b0, b1, pbh[i], pbl[i]);
        }
    };
    auto r2s = [&](int stage) {
        char* s = smem + stage * STAGE_BYTES;
#pragma unroll
        for (int i = 0; i < 8; ++i) {
            const int row = lr + i * 16;
            const int off = row * (LDR * 2) + lc * 2;
            *(uint32_t*)(s + 0 * MAT_BYTES + off) = pah[i];
            *(uint32_t*)(s + 1 * MAT_BYTES + off) = pal[i];
            *(uint32_t*)(s + 2 * MAT_BYTES + off) = pbh[i];
            *(uint32_t*)(s + 3 * MAT_BYTES + off) = pbl[i];
        }
    };

    // ---- prologue
    prefetch(0);
    r2s(0);
    __syncthreads();

    for (int kc = 0; kc < nKC; ++kc) {
        const int cur = kc & 1;
        const bool has_next = (kc + 1 < nKC);
        if (has_next) prefetch(kc + 1);

        const uint32_t sAhi = sbase + cur * STAGE_BYTES;
        const uint32_t sAlo = sAhi + MAT_BYTES;
        const uint32_t sBhi = sAhi + 2 * MAT_BYTES;
        const uint32_t sBlo = sAhi + 3 * MAT_BYTES;

#pragma unroll
        for (int k16 = 0; k16 < 2; ++k16) {
            const uint32_t kb = k16 * 32;  // 16 bf16 = 32 bytes

            uint32_t ah[4][4], al[4][4];
#pragma unroll
            for (int mi = 0; mi < 4; ++mi) {
                const uint32_t rowb =
                    (uint32_t)(wm * 64 + mi * 16 + (lane & 15)) * (LDR * 2);
                const uint32_t off = rowb + ((lane >> 4) * 16) + kb;
                ldsm4(ah[mi], sAhi + off);
                ldsm4(al[mi], sAlo + off);
            }
            uint32_t bh[4][2], bl[4][2];
#pragma unroll
            for (int jj = 0; jj < 2; ++jj) {
                const uint32_t nrow =
                    (uint32_t)(wn * 32 + jj * 16 + ((lane >> 4) & 1) * 8 +
                               (lane & 7));
                const uint32_t off =
                    nrow * (LDR * 2) + (((lane >> 3) & 1) * 16) + kb;
                uint32_t t[4];
                ldsm4(t, sBhi + off);
                bh[jj * 2][0] = t[0]; bh[jj * 2][1] = t[1];
                bh[jj * 2 + 1][0] = t[2]; bh[jj * 2 + 1][1] = t[3];
                ldsm4(t, sBlo + off);
                bl[jj * 2][0] = t[0]; bl[jj * 2][1] = t[1];
                bl[jj * 2 + 1][0] = t[2]; bl[jj * 2 + 1][1] = t[3];
            }
#pragma unroll
            for (int mi = 0; mi < 4; ++mi)
#pragma unroll
                for (int nj = 0; nj < 4; ++nj) {
                    mma16816(acc[mi][nj], ah[mi], bh[nj]);
                    mma16816(acc[mi][nj], ah[mi], bl[nj]);
                    mma16816(acc[mi][nj], al[mi], bh[nj]);
                }
        }

        if (has_next) r2s(cur ^ 1);
        __syncthreads();
    }

    // ---- epilogue: fragment layout c0,c1 = (row, 2c..2c+1), c2,c3 = row+8
    const int rbase = m0 + wm * 64 + (lane >> 2);
    const int cbase = n0 + wn * 32 + (lane & 3) * 2;
#pragma unroll
    for (int mi = 0; mi < 4; ++mi) {
#pragma unroll
        for (int nj = 0; nj < 4; ++nj) {
            const int col = cbase + nj * 8;
            const int row = rbase + mi * 16;
            if (col < N) {
                const float bb0 = bias[col];
                C[(size_t)row * N + col] = acc[mi][nj][0] + bb0;
                C[(size_t)(row + 8) * N + col] = acc[mi][nj][2] + bb0;
            }
            if (col + 1 < N) {
                const float bb1 = bias[col + 1];
                C[(size_t)row * N + col + 1] = acc[mi][nj][1] + bb1;
                C[(size_t)(row + 8) * N + col + 1] = acc[mi][nj][3] + bb1;
            }
        }
    }
}

// ---------------------------------------------------------------------------
// LSTM scan over batch axis. One block per t (grid 512, 256 threads).
// h reads vectorized to float4 LDS (12 x LDS.128 + 2 scalar per dot).
// ---------------------------------------------------------------------------
__global__ __launch_bounds__(256) void lstm_scan(
    const float* __restrict__ W_hh, const float* __restrict__ b_hh)
{
    __shared__ __align__(16) float h_s[HH + 2];
    __shared__ float g_s[G4];

    const int t = blockIdx.x;
    const int j = threadIdx.x;

    float w[HH];
    float bj = 0.f;
    if (j < G4) {
#pragma unroll
        for (int k = 0; k < HH; ++k) w[k] = W_hh[j * HH + k];
        bj = b_hh[j];
    }
    float c = 0.f;
    if (j < HH + 2) h_s[j] = 0.f;
    __syncthreads();

    for (int b = 0; b < BB; ++b) {
        if (j < G4) {
            float g0 = g_xg[((size_t)b * TT + t) * G4 + j] + bj;
            float g1 = 0.f, g2 = 0.f, g3 = 0.f;
#pragma unroll
            for (int k = 0; k < 48; k += 4) {
                float4 hv = *(const float4*)&h_s[k];
                g0 += w[k + 0] * hv.x;
                g1 += w[k + 1] * hv.y;
                g2 += w[k + 2] * hv.z;
                g3 += w[k + 3] * hv.w;
            }
            g0 += w[48] * h_s[48];
            g1 += w[49] * h_s[49];
            g_s[j] = (g0 + g1) + (g2 + g3);
        }
        __syncthreads();
        if (j < HH) {
            float gi = g_s[j];
            float gf = g_s[j + HH];
            float gg = g_s[j + 2 * HH];
            float go = g_s[j + 3 * HH];
            float si = 1.f / (1.f + expf(-gi));
            float sf = 1.f / (1.f + expf(-gf));
            float so = 1.f / (1.f + expf(-go));
            float tg = tanhf(gg);
            c = sf * c + si * tg;
            float hv = so * tanhf(c);
            h_s[j] = hv;
            g_hs[((size_t)b * TT + t) * HH + j] = hv;
        }
        __syncthreads();
    }
}

// ---------------------------------------------------------------------------
extern "C" void kernel_launch(void* const* d_in, const int* in_sizes, int n_in,
                              void* d_out, int out_size)
{
    const float* x     = (const float*)d_in[0];  // (B,T,F)
    const float* W_ih  = (const float*)d_in[1];  // (200,513)
    const float* W_hh  = (const float*)d_in[2];  // (200,50)
    const float* b_ih  = (const float*)d_in[3];  // (200,)
    const float* b_hh  = (const float*)d_in[4];  // (200,)
    const float* W_out = (const float*)d_in[5];  // (513,50)
    const float* b_out = (const float*)d_in[6];  // (513,)
    float* out = (float*)d_out;                  // (B,T,F)

    float* xg = nullptr;
    float* hs = nullptr;
    cudaGetSymbolAddress((void**)&xg, g_xg);
    cudaGetSymbolAddress((void**)&hs, g_hs);

    cudaFuncSetAttribute(gemm_mma_nt,
                         cudaFuncAttributeMaxDynamicSharedMemorySize,
                         SMEM_TOTAL);

    // 1) xg = x @ W_ih^T + b_ih   (M=32768, N=200, K=513) — tensor cores
    {
        dim3 grid(MROWS / 128, (G4 + 127) / 128);   // (256, 2)
        gemm_mma_nt<<<grid, 256, SMEM_TOTAL>>>(x, W_ih, b_ih, xg, MROWS, G4, FF);
    }
    // 2) LSTM scan over batch axis (512 independent chains)
    lstm_scan<<<TT, 256>>>(W_hh, b_hh);

    // 3) out = hs @ W_out^T + b_out  (M=32768, N=513, K=50) — tensor cores
    {
        dim3 grid(MROWS / 128, (FF + 127) / 128);   // (256, 5)
        gemm_mma_nt<<<grid, 256, SMEM_TOTAL>>>(hs, W_out, b_out, out, MROWS, FF, HH);
    }
}

// round 6
// speedup vs baseline: 1.0406x; 1.0406x over previous
#include <cuda_runtime.h>
#include <cuda_bf16.h>
#include <math.h>
#include <stdint.h>

// Problem constants (fixed by the reference)
#define BB 64
#define TT 512
#define FF 513
#define HH 50
#define G4 200          // 4*H
#define MROWS (BB*TT)   // 32768

#define KP1 544         // K=513 padded to 17*32
#define NKC1 17
#define KP2 64          // K=50 padded to 2*32
#define NKC2 2
#define NP1 256         // W_ih rows padded (grid.y=2)
#define NP2 640         // W_out rows padded (grid.y=5)

// Scratch (static device globals — no allocation in kernel_launch)
__device__ float g_xg[MROWS * G4];
__device__ __nv_bfloat16 g_xhi[MROWS * KP1];
__device__ __nv_bfloat16 g_xlo[MROWS * KP1];
__device__ __nv_bfloat16 g_wihhi[NP1 * KP1];
__device__ __nv_bfloat16 g_wihlo[NP1 * KP1];
__device__ __nv_bfloat16 g_hshi[MROWS * KP2];
__device__ __nv_bfloat16 g_hslo[MROWS * KP2];
__device__ __nv_bfloat16 g_wohi[NP2 * KP2];
__device__ __nv_bfloat16 g_wolo[NP2 * KP2];

// ===========================================================================
// PTX helpers
// ===========================================================================
__device__ __forceinline__ uint32_t smem_u32(const void* p) {
    uint32_t a;
    asm("{ .reg .u64 t; cvta.to.shared.u64 t, %1; cvt.u32.u64 %0, t; }"
        : "=r"(a) : "l"(p));
    return a;
}
__device__ __forceinline__ void ldsm4(uint32_t* r, uint32_t a) {
    asm volatile("ldmatrix.sync.aligned.m8n8.x4.shared.b16 {%0,%1,%2,%3}, [%4];"
                 : "=r"(r[0]), "=r"(r[1]), "=r"(r[2]), "=r"(r[3]) : "r"(a));
}
__device__ __forceinline__ void mma16816(float* c, const uint32_t* a,
                                         const uint32_t* b) {
    asm volatile(
        "mma.sync.aligned.m16n8k16.row.col.f32.bf16.bf16.f32 "
        "{%0,%1,%2,%3}, {%4,%5,%6,%7}, {%8,%9}, {%0,%1,%2,%3};"
        : "+f"(c[0]), "+f"(c[1]), "+f"(c[2]), "+f"(c[3])
        : "r"(a[0]), "r"(a[1]), "r"(a[2]), "r"(a[3]), "r"(b[0]), "r"(b[1]));
}
__device__ __forceinline__ void cpasync16(uint32_t dst, const void* src) {
    asm volatile("cp.async.cg.shared.global [%0], [%1], 16;"
                 :: "r"(dst), "l"(src));
}
#define CP_COMMIT() asm volatile("cp.async.commit_group;" ::: "memory")
#define CP_WAIT0()  asm volatile("cp.async.wait_group 0;" ::: "memory")

// ===========================================================================
// Convert fp32 (srcR x srcC) -> zero-padded bf16 hi/lo (dstR x dstC)
// Two columns per thread (paired 4B stores).
// ===========================================================================
__global__ void conv_split(const float* __restrict__ src,
                           __nv_bfloat16* __restrict__ hi,
                           __nv_bfloat16* __restrict__ lo,
                           int srcR, int srcC, int dstR, int dstC)
{
    int idx = blockIdx.x * blockDim.x + threadIdx.x;  // pair index
    int total = dstR * (dstC >> 1);
    if (idx >= total) return;
    int r = idx / (dstC >> 1);
    int c = (idx % (dstC >> 1)) * 2;
    float v0 = (r < srcR && c < srcC) ? src[(size_t)r * srcC + c] : 0.f;
    float v1 = (r < srcR && c + 1 < srcC) ? src[(size_t)r * srcC + c + 1] : 0.f;
    __nv_bfloat16 h0 = __float2bfloat16(v0);
    __nv_bfloat16 h1 = __float2bfloat16(v1);
    __nv_bfloat162 hv(h0, h1);
    __nv_bfloat162 lv(__float2bfloat16(v0 - __bfloat162float(h0)),
                      __float2bfloat16(v1 - __bfloat162float(h1)));
    *(__nv_bfloat162*)&hi[(size_t)r * dstC + c] = hv;
    *(__nv_bfloat162*)&lo[(size_t)r * dstC + c] = lv;
}

// ===========================================================================
// Pure-bf16 NT GEMM with bias, split accumulation:
//   C[m,n] = sum_k (Ahi+Alo)[m,k]*(Bhi+Blo)[n,k] + bias[n]   (lo*lo dropped)
// Block 128x128, KC=32, cp.async double-buffered. 8 warps 2(m)x4(n).
// smem rows 40 bf16 (80 B): conflict-free ldmatrix.
// ===========================================================================
#define LDR 40
#define MAT_BYTES (128 * LDR * 2)        // 10240
#define STAGE_BYTES (4 * MAT_BYTES)      // 40960
#define SMEM_TOTAL (2 * STAGE_BYTES)     // 81920

__global__ __launch_bounds__(256) void gemm_bf16_nt(
    const __nv_bfloat16* __restrict__ Ahi, const __nv_bfloat16* __restrict__ Alo,
    const __nv_bfloat16* __restrict__ Bhi, const __nv_bfloat16* __restrict__ Blo,
    const float* __restrict__ bias, float* __restrict__ C,
    int N, int Kp, int nKC)
{
    extern __shared__ __align__(16) char smem[];
    const uint32_t sbase = smem_u32(smem);

    const int tid  = threadIdx.x;
    const int lane = tid & 31;
    const int wid  = tid >> 5;
    const int wm   = wid & 1;
    const int wn   = wid >> 1;

    const int m0 = blockIdx.x * 128;
    const int n0 = blockIdx.y * 128;

    float acc[4][4][4];
#pragma unroll
    for (int i = 0; i < 4; ++i)
#pragma unroll
        for (int j = 0; j < 4; ++j)
#pragma unroll
            for (int q = 0; q < 4; ++q) acc[i][j][q] = 0.f;

    // cp.async issue for one stage: 512 16B-chunks per matrix-half
    auto issue = [&](int kc, int stage) {
        const uint32_t s32 = sbase + stage * STAGE_BYTES;
#pragma unroll
        for (int i = 0; i < 2; ++i) {
            const int chunk = tid + i * 256;      // 0..511
            const int row = chunk >> 2;
            const int g = chunk & 3;
            const uint32_t dofs = row * 80 + g * 16;
            const size_t aofs = (size_t)(m0 + row) * Kp + kc * 32 + g * 8;
            const size_t bofs = (size_t)(n0 + row) * Kp + kc * 32 + g * 8;
            cpasync16(s32 + 0 * MAT_BYTES + dofs, Ahi + aofs);
            cpasync16(s32 + 1 * MAT_BYTES + dofs, Alo + aofs);
            cpasync16(s32 + 2 * MAT_BYTES + dofs, Bhi + bofs);
            cpasync16(s32 + 3 * MAT_BYTES + dofs, Blo + bofs);
        }
    };

    issue(0, 0);
    CP_COMMIT();

    for (int kc = 0; kc < nKC; ++kc) {
        const int cur = kc & 1;
        CP_WAIT0();
        __syncthreads();   // data ready; all warps past previous compute

        if (kc + 1 < nKC) {
            issue(kc + 1, cur ^ 1);
            CP_COMMIT();
        }

        const uint32_t sAhi = sbase + cur * STAGE_BYTES;
        const uint32_t sAlo = sAhi + MAT_BYTES;
        const uint32_t sBhi = sAhi + 2 * MAT_BYTES;
        const uint32_t sBlo = sAhi + 3 * MAT_BYTES;

#pragma unroll
        for (int k16 = 0; k16 < 2; ++k16) {
            const uint32_t kb = k16 * 32;

            uint32_t ah[4][4], al[4][4];
#pragma unroll
            for (int mi = 0; mi < 4; ++mi) {
                const uint32_t rowb =
                    (uint32_t)(wm * 64 + mi * 16 + (lane & 15)) * 80;
                const uint32_t off = rowb + ((lane >> 4) * 16) + kb;
                ldsm4(ah[mi], sAhi + off);
                ldsm4(al[mi], sAlo + off);
            }
            uint32_t bh[4][2], bl[4][2];
#pragma unroll
            for (int jj = 0; jj < 2; ++jj) {
                const uint32_t nrow =
                    (uint32_t)(wn * 32 + jj * 16 + ((lane >> 4) & 1) * 8 +
                               (lane & 7));
                const uint32_t off = nrow * 80 + (((lane >> 3) & 1) * 16) + kb;
                uint32_t t[4];
                ldsm4(t, sBhi + off);
                bh[jj * 2][0] = t[0]; bh[jj * 2][1] = t[1];
                bh[jj * 2 + 1][0] = t[2]; bh[jj * 2 + 1][1] = t[3];
                ldsm4(t, sBlo + off);
                bl[jj * 2][0] = t[0]; bl[jj * 2][1] = t[1];
                bl[jj * 2 + 1][0] = t[2]; bl[jj * 2 + 1][1] = t[3];
            }
#pragma unroll
            for (int mi = 0; mi < 4; ++mi)
#pragma unroll
                for (int nj = 0; nj < 4; ++nj) {
                    mma16816(acc[mi][nj], ah[mi], bh[nj]);
                    mma16816(acc[mi][nj], ah[mi], bl[nj]);
                    mma16816(acc[mi][nj], al[mi], bh[nj]);
                }
        }
    }

    // epilogue
    const int rbase = m0 + wm * 64 + (lane >> 2);
    const int cbase = n0 + wn * 32 + (lane & 3) * 2;
#pragma unroll
    for (int mi = 0; mi < 4; ++mi) {
#pragma unroll
        for (int nj = 0; nj < 4; ++nj) {
            const int col = cbase + nj * 8;
            const int row = rbase + mi * 16;
            if (col < N) {
                const float bb0 = bias[col];
                C[(size_t)row * N + col] = acc[mi][nj][0] + bb0;
                C[(size_t)(row + 8) * N + col] = acc[mi][nj][2] + bb0;
            }
            if (col + 1 < N) {
                const float bb1 = bias[col + 1];
                C[(size_t)row * N + col + 1] = acc[mi][nj][1] + bb1;
                C[(size_t)(row + 8) * N + col + 1] = acc[mi][nj][3] + bb1;
            }
        }
    }
}

// ---------------------------------------------------------------------------
// LSTM scan over batch axis. One block per t (grid 512, 256 threads).
// Writes h as bf16 hi/lo directly into GEMM2's padded A arrays.
// ---------------------------------------------------------------------------
__global__ __launch_bounds__(256) void lstm_scan(
    const float* __restrict__ W_hh, const float* __restrict__ b_hh)
{
    __shared__ __align__(16) float h_s[HH + 2];
    __shared__ float g_s[G4];

    const int t = blockIdx.x;
    const int j = threadIdx.x;

    float w[HH];
    float bj = 0.f;
    if (j < G4) {
#pragma unroll
        for (int k = 0; k < HH; ++k) w[k] = W_hh[j * HH + k];
        bj = b_hh[j];
    }
    float c = 0.f;
    if (j < HH + 2) h_s[j] = 0.f;
    __syncthreads();

    for (int b = 0; b < BB; ++b) {
        if (j < G4) {
            float g0 = g_xg[((size_t)b * TT + t) * G4 + j] + bj;
            float g1 = 0.f, g2 = 0.f, g3 = 0.f;
#pragma unroll
            for (int k = 0; k < 48; k += 4) {
                float4 hv = *(const float4*)&h_s[k];
                g0 += w[k + 0] * hv.x;
                g1 += w[k + 1] * hv.y;
                g2 += w[k + 2] * hv.z;
                g3 += w[k + 3] * hv.w;
            }
            g0 += w[48] * h_s[48];
            g1 += w[49] * h_s[49];
            g_s[j] = (g0 + g1) + (g2 + g3);
        }
        __syncthreads();
        if (j < KP2) {   // 64 threads: 50 real + 14 zero-pad cols
            float hv = 0.f;
            if (j < HH) {
                float gi = g_s[j];
                float gf = g_s[j + HH];
                float gg = g_s[j + 2 * HH];
                float go = g_s[j + 3 * HH];
                float si = 1.f / (1.f + expf(-gi));
                float sf = 1.f / (1.f + expf(-gf));
                float so = 1.f / (1.f + expf(-go));
                float tg = tanhf(gg);
                c = sf * c + si * tg;
                hv = so * tanhf(c);
                h_s[j] = hv;
            }
            __nv_bfloat16 hh = __float2bfloat16(hv);
            const size_t o = ((size_t)b * TT + t) * KP2 + j;
            g_hshi[o] = hh;
            g_hslo[o] = __float2bfloat16(hv - __bfloat162float(hh));
        }
        __syncthreads();
    }
}

// ---------------------------------------------------------------------------
extern "C" void kernel_launch(void* const* d_in, const int* in_sizes, int n_in,
                              void* d_out, int out_size)
{
    const float* x     = (const float*)d_in[0];
    const float* W_ih  = (const float*)d_in[1];
    const float* W_hh  = (const float*)d_in[2];
    const float* b_ih  = (const float*)d_in[3];
    const float* b_hh  = (const float*)d_in[4];
    const float* W_out = (const float*)d_in[5];
    const float* b_out = (const float*)d_in[6];
    float* out = (float*)d_out;

    float* xg = nullptr;
    __nv_bfloat16 *xhi, *xlo, *wihhi, *wihlo, *hshi, *hslo, *wohi, *wolo;
    cudaGetSymbolAddress((void**)&xg, g_xg);
    cudaGetSymbolAddress((void**)&xhi, g_xhi);
    cudaGetSymbolAddress((void**)&xlo, g_xlo);
    cudaGetSymbolAddress((void**)&wihhi, g_wihhi);
    cudaGetSymbolAddress((void**)&wihlo, g_wihlo);
    cudaGetSymbolAddress((void**)&hshi, g_hshi);
    cudaGetSymbolAddress((void**)&hslo, g_hslo);
    cudaGetSymbolAddress((void**)&wohi, g_wohi);
    cudaGetSymbolAddress((void**)&wolo, g_wolo);

    cudaFuncSetAttribute(gemm_bf16_nt,
                         cudaFuncAttributeMaxDynamicSharedMemorySize,
                         SMEM_TOTAL);

    // 0) conversions (hi/lo bf16, zero-padded)
    {
        int n1 = MROWS * (KP1 / 2);
        conv_split<<<(n1 + 255) / 256, 256>>>(x, xhi, xlo, MROWS, FF, MROWS, KP1);
        int n2 = NP1 * (KP1 / 2);
        conv_split<<<(n2 + 255) / 256, 256>>>(W_ih, wihhi, wihlo, G4, FF, NP1, KP1);
        int n3 = NP2 * (KP2 / 2);
        conv_split<<<(n3 + 255) / 256, 256>>>(W_out, wohi, wolo, FF, HH, NP2, KP2);
    }

    // 1) xg = x @ W_ih^T + b_ih   (M=32768, N=200, Kp=544)
    {
        dim3 grid(MROWS / 128, NP1 / 128);   // (256, 2)
        gemm_bf16_nt<<<grid, 256, SMEM_TOTAL>>>(xhi, xlo, wihhi, wihlo,
                                                b_ih, xg, G4, KP1, NKC1);
    }
    // 2) LSTM scan (writes hs as bf16 hi/lo)
    lstm_scan<<<TT, 256>>>(W_hh, b_hh);

    // 3) out = hs @ W_out^T + b_out  (M=32768, N=513, Kp=64)
    {
        dim3 grid(MROWS / 128, NP2 / 128);   // (256, 5)
        gemm_bf16_nt<<<grid, 256, SMEM_TOTAL>>>(hshi, hslo, wohi, wolo,
                                                b_out, out, FF, KP2, NKC2);
    }
}

// round 7
// speedup vs baseline: 1.1448x; 1.1001x over previous
#include <cuda_runtime.h>
#include <cuda_bf16.h>
#include <math.h>
#include <stdint.h>

// Problem constants (fixed by the reference)
#define BB 64
#define TT 512
#define FF 513
#define HH 50
#define G4 200          // 4*H
#define MROWS (BB*TT)   // 32768

#define KP1 544         // K=513 padded to 17*32
#define NKC1 17
#define KP2 64          // K=50 padded to 2*32
#define NKC2 2
#define NP1 256         // W_ih rows padded (grid.y=2)
#define NP2 640         // W_out rows padded (grid.y=5)

// Scratch (static device globals — no allocation in kernel_launch)
__device__ float g_xg[MROWS * G4];
__device__ __nv_bfloat16 g_xhi[MROWS * KP1];
__device__ __nv_bfloat16 g_xlo[MROWS * KP1];
__device__ __nv_bfloat16 g_wihhi[NP1 * KP1];
__device__ __nv_bfloat16 g_wihlo[NP1 * KP1];
__device__ __nv_bfloat16 g_hshi[MROWS * KP2];
__device__ __nv_bfloat16 g_hslo[MROWS * KP2];
__device__ __nv_bfloat16 g_wohi[NP2 * KP2];
__device__ __nv_bfloat16 g_wolo[NP2 * KP2];

// ===========================================================================
// PTX helpers
// ===========================================================================
__device__ __forceinline__ uint32_t smem_u32(const void* p) {
    uint32_t a;
    asm("{ .reg .u64 t; cvta.to.shared.u64 t, %1; cvt.u32.u64 %0, t; }"
        : "=r"(a) : "l"(p));
    return a;
}
__device__ __forceinline__ void ldsm4(uint32_t* r, uint32_t a) {
    asm volatile("ldmatrix.sync.aligned.m8n8.x4.shared.b16 {%0,%1,%2,%3}, [%4];"
                 : "=r"(r[0]), "=r"(r[1]), "=r"(r[2]), "=r"(r[3]) : "r"(a));
}
__device__ __forceinline__ void mma16816(float* c, const uint32_t* a,
                                         const uint32_t* b) {
    asm volatile(
        "mma.sync.aligned.m16n8k16.row.col.f32.bf16.bf16.f32 "
        "{%0,%1,%2,%3}, {%4,%5,%6,%7}, {%8,%9}, {%0,%1,%2,%3};"
        : "+f"(c[0]), "+f"(c[1]), "+f"(c[2]), "+f"(c[3])
        : "r"(a[0]), "r"(a[1]), "r"(a[2]), "r"(a[3]), "r"(b[0]), "r"(b[1]));
}
__device__ __forceinline__ void cpasync16(uint32_t dst, const void* src) {
    asm volatile("cp.async.cg.shared.global [%0], [%1], 16;"
                 :: "r"(dst), "l"(src));
}
#define CP_COMMIT() asm volatile("cp.async.commit_group;" ::: "memory")
#define CP_WAIT0()  asm volatile("cp.async.wait_group 0;" ::: "memory")

// ===========================================================================
// Convert fp32 (srcR x srcC) -> zero-padded bf16 hi/lo (dstR x dstC)
// ===========================================================================
__global__ void conv_split(const float* __restrict__ src,
                           __nv_bfloat16* __restrict__ hi,
                           __nv_bfloat16* __restrict__ lo,
                           int srcR, int srcC, int dstR, int dstC)
{
    int idx = blockIdx.x * blockDim.x + threadIdx.x;  // pair index
    int total = dstR * (dstC >> 1);
    if (idx >= total) return;
    int r = idx / (dstC >> 1);
    int c = (idx % (dstC >> 1)) * 2;
    float v0 = (r < srcR && c < srcC) ? src[(size_t)r * srcC + c] : 0.f;
    float v1 = (r < srcR && c + 1 < srcC) ? src[(size_t)r * srcC + c + 1] : 0.f;
    __nv_bfloat16 h0 = __float2bfloat16(v0);
    __nv_bfloat16 h1 = __float2bfloat16(v1);
    __nv_bfloat162 hv(h0, h1);
    __nv_bfloat162 lv(__float2bfloat16(v0 - __bfloat162float(h0)),
                      __float2bfloat16(v1 - __bfloat162float(h1)));
    *(__nv_bfloat162*)&hi[(size_t)r * dstC + c] = hv;
    *(__nv_bfloat162*)&lo[(size_t)r * dstC + c] = lv;
}

// ===========================================================================
// Pure-bf16 NT GEMM with bias, split accumulation:
//   C[m,n] = sum_k (Ahi+Alo)[m,k]*(Bhi+Blo)[n,k] + bias[n]   (lo*lo dropped)
// Block 128x128, KC=32, cp.async double-buffered. 8 warps 2(m)x4(n).
// __launch_bounds__(256,2): regs<=128 -> 2 CTAs/SM (smem 2x80KB fits).
// ===========================================================================
#define LDR 40
#define MAT_BYTES (128 * LDR * 2)        // 10240
#define STAGE_BYTES (4 * MAT_BYTES)      // 40960
#define SMEM_TOTAL (2 * STAGE_BYTES)     // 81920

__global__ __launch_bounds__(256, 2) void gemm_bf16_nt(
    const __nv_bfloat16* __restrict__ Ahi, const __nv_bfloat16* __restrict__ Alo,
    const __nv_bfloat16* __restrict__ Bhi, const __nv_bfloat16* __restrict__ Blo,
    const float* __restrict__ bias, float* __restrict__ C,
    int N, int Kp, int nKC)
{
    extern __shared__ __align__(16) char smem[];
    const uint32_t sbase = smem_u32(smem);

    const int tid  = threadIdx.x;
    const int lane = tid & 31;
    const int wid  = tid >> 5;
    const int wm   = wid & 1;
    const int wn   = wid >> 1;

    const int m0 = blockIdx.x * 128;
    const int n0 = blockIdx.y * 128;

    float acc[4][4][4];
#pragma unroll
    for (int i = 0; i < 4; ++i)
#pragma unroll
        for (int j = 0; j < 4; ++j)
#pragma unroll
            for (int q = 0; q < 4; ++q) acc[i][j][q] = 0.f;

    // cp.async issue for one stage: 512 16B-chunks per matrix-half
    auto issue = [&](int kc, int stage) {
        const uint32_t s32 = sbase + stage * STAGE_BYTES;
#pragma unroll
        for (int i = 0; i < 2; ++i) {
            const int chunk = tid + i * 256;      // 0..511
            const int row = chunk >> 2;
            const int g = chunk & 3;
            const uint32_t dofs = row * 80 + g * 16;
            const size_t aofs = (size_t)(m0 + row) * Kp + kc * 32 + g * 8;
            const size_t bofs = (size_t)(n0 + row) * Kp + kc * 32 + g * 8;
            cpasync16(s32 + 0 * MAT_BYTES + dofs, Ahi + aofs);
            cpasync16(s32 + 1 * MAT_BYTES + dofs, Alo + aofs);
            cpasync16(s32 + 2 * MAT_BYTES + dofs, Bhi + bofs);
            cpasync16(s32 + 3 * MAT_BYTES + dofs, Blo + bofs);
        }
    };

    issue(0, 0);
    CP_COMMIT();

    for (int kc = 0; kc < nKC; ++kc) {
        const int cur = kc & 1;
        CP_WAIT0();
        __syncthreads();   // data ready; all warps past previous compute

        if (kc + 1 < nKC) {
            issue(kc + 1, cur ^ 1);
            CP_COMMIT();
        }

        const uint32_t sAhi = sbase + cur * STAGE_BYTES;
        const uint32_t sAlo = sAhi + MAT_BYTES;
        const uint32_t sBhi = sAhi + 2 * MAT_BYTES;
        const uint32_t sBlo = sAhi + 3 * MAT_BYTES;

#pragma unroll
        for (int k16 = 0; k16 < 2; ++k16) {
            const uint32_t kb = k16 * 32;

            uint32_t ah[4][4], al[4][4];
#pragma unroll
            for (int mi = 0; mi < 4; ++mi) {
                const uint32_t rowb =
                    (uint32_t)(wm * 64 + mi * 16 + (lane & 15)) * 80;
                const uint32_t off = rowb + ((lane >> 4) * 16) + kb;
                ldsm4(ah[mi], sAhi + off);
                ldsm4(al[mi], sAlo + off);
            }
            uint32_t bh[4][2], bl[4][2];
#pragma unroll
            for (int jj = 0; jj < 2; ++jj) {
                const uint32_t nrow =
                    (uint32_t)(wn * 32 + jj * 16 + ((lane >> 4) & 1) * 8 +
                               (lane & 7));
                const uint32_t off = nrow * 80 + (((lane >> 3) & 1) * 16) + kb;
                uint32_t t[4];
                ldsm4(t, sBhi + off);
                bh[jj * 2][0] = t[0]; bh[jj * 2][1] = t[1];
                bh[jj * 2 + 1][0] = t[2]; bh[jj * 2 + 1][1] = t[3];
                ldsm4(t, sBlo + off);
                bl[jj * 2][0] = t[0]; bl[jj * 2][1] = t[1];
                bl[jj * 2 + 1][0] = t[2]; bl[jj * 2 + 1][1] = t[3];
            }
#pragma unroll
            for (int mi = 0; mi < 4; ++mi)
#pragma unroll
                for (int nj = 0; nj < 4; ++nj) {
                    mma16816(acc[mi][nj], ah[mi], bh[nj]);
                    mma16816(acc[mi][nj], ah[mi], bl[nj]);
                    mma16816(acc[mi][nj], al[mi], bh[nj]);
                }
        }
    }

    // epilogue
    const int rbase = m0 + wm * 64 + (lane >> 2);
    const int cbase = n0 + wn * 32 + (lane & 3) * 2;
#pragma unroll
    for (int mi = 0; mi < 4; ++mi) {
#pragma unroll
        for (int nj = 0; nj < 4; ++nj) {
            const int col = cbase + nj * 8;
            const int row = rbase + mi * 16;
            if (col < N) {
                const float bb0 = bias[col];
                C[(size_t)row * N + col] = acc[mi][nj][0] + bb0;
                C[(size_t)(row + 8) * N + col] = acc[mi][nj][2] + bb0;
            }
            if (col + 1 < N) {
                const float bb1 = bias[col + 1];
                C[(size_t)row * N + col + 1] = acc[mi][nj][1] + bb1;
                C[(size_t)(row + 8) * N + col + 1] = acc[mi][nj][3] + bb1;
            }
        }
    }
}

// ---------------------------------------------------------------------------
// LSTM scan over batch axis. One block per t (grid 512, 256 threads).
// Writes h as bf16 hi/lo directly into GEMM2's padded A arrays.
// ---------------------------------------------------------------------------
__global__ __launch_bounds__(256) void lstm_scan(
    const float* __restrict__ W_hh, const float* __restrict__ b_hh)
{
    __shared__ __align__(16) float h_s[HH + 2];
    __shared__ float g_s[G4];

    const int t = blockIdx.x;
    const int j = threadIdx.x;

    float w[HH];
    float bj = 0.f;
    if (j < G4) {
#pragma unroll
        for (int k = 0; k < HH; ++k) w[k] = W_hh[j * HH + k];
        bj = b_hh[j];
    }
    float c = 0.f;
    if (j < HH + 2) h_s[j] = 0.f;
    __syncthreads();

    for (int b = 0; b < BB; ++b) {
        if (j < G4) {
            float g0 = g_xg[((size_t)b * TT + t) * G4 + j] + bj;
            float g1 = 0.f, g2 = 0.f, g3 = 0.f;
#pragma unroll
            for (int k = 0; k < 48; k += 4) {
                float4 hv = *(const float4*)&h_s[k];
                g0 += w[k + 0] * hv.x;
                g1 += w[k + 1] * hv.y;
                g2 += w[k + 2] * hv.z;
                g3 += w[k + 3] * hv.w;
            }
            g0 += w[48] * h_s[48];
            g1 += w[49] * h_s[49];
            g_s[j] = (g0 + g1) + (g2 + g3);
        }
        __syncthreads();
        if (j < KP2) {   // 64 threads: 50 real + 14 zero-pad cols
            float hv = 0.f;
            if (j < HH) {
                float gi = g_s[j];
                float gf = g_s[j + HH];
                float gg = g_s[j + 2 * HH];
                float go = g_s[j + 3 * HH];
                float si = 1.f / (1.f + expf(-gi));
                float sf = 1.f / (1.f + expf(-gf));
                float so = 1.f / (1.f + expf(-go));
                float tg = tanhf(gg);
                c = sf * c + si * tg;
                hv = so * tanhf(c);
                h_s[j] = hv;
            }
            __nv_bfloat16 hh = __float2bfloat16(hv);
            const size_t o = ((size_t)b * TT + t) * KP2 + j;
            g_hshi[o] = hh;
            g_hslo[o] = __float2bfloat16(hv - __bfloat162float(hh));
        }
        __syncthreads();
    }
}

// ---------------------------------------------------------------------------
extern "C" void kernel_launch(void* const* d_in, const int* in_sizes, int n_in,
                              void* d_out, int out_size)
{
    const float* x     = (const float*)d_in[0];
    const float* W_ih  = (const float*)d_in[1];
    const float* W_hh  = (const float*)d_in[2];
    const float* b_ih  = (const float*)d_in[3];
    const float* b_hh  = (const float*)d_in[4];
    const float* W_out = (const float*)d_in[5];
    const float* b_out = (const float*)d_in[6];
    float* out = (float*)d_out;

    float* xg = nullptr;
    __nv_bfloat16 *xhi, *xlo, *wihhi, *wihlo, *hshi, *hslo, *wohi, *wolo;
    cudaGetSymbolAddress((void**)&xg, g_xg);
    cudaGetSymbolAddress((void**)&xhi, g_xhi);
    cudaGetSymbolAddress((void**)&xlo, g_xlo);
    cudaGetSymbolAddress((void**)&wihhi, g_wihhi);
    cudaGetSymbolAddress((void**)&wihlo, g_wihlo);
    cudaGetSymbolAddress((void**)&hshi, g_hshi);
    cudaGetSymbolAddress((void**)&hslo, g_hslo);
    cudaGetSymbolAddress((void**)&wohi, g_wohi);
    cudaGetSymbolAddress((void**)&wolo, g_wolo);

    cudaFuncSetAttribute(gemm_bf16_nt,
                         cudaFuncAttributeMaxDynamicSharedMemorySize,
                         SMEM_TOTAL);

    // 0) conversions (hi/lo bf16, zero-padded)
    {
        int n1 = MROWS * (KP1 / 2);
        conv_split<<<(n1 + 255) / 256, 256>>>(x, xhi, xlo, MROWS, FF, MROWS, KP1);
        int n2 = NP1 * (KP1 / 2);
        conv_split<<<(n2 + 255) / 256, 256>>>(W_ih, wihhi, wihlo, G4, FF, NP1, KP1);
        int n3 = NP2 * (KP2 / 2);
        conv_split<<<(n3 + 255) / 256, 256>>>(W_out, wohi, wolo, FF, HH, NP2, KP2);
    }

    // 1) xg = x @ W_ih^T + b_ih   (M=32768, N=200, Kp=544)
    {
        dim3 grid(MROWS / 128, NP1 / 128);   // (256, 2)
        gemm_bf16_nt<<<grid, 256, SMEM_TOTAL>>>(xhi, xlo, wihhi, wihlo,
                                                b_ih, xg, G4, KP1, NKC1);
    }
    // 2) LSTM scan (writes hs as bf16 hi/lo)
    lstm_scan<<<TT, 256>>>(W_hh, b_hh);

    // 3) out = hs @ W_out^T + b_out  (M=32768, N=513, Kp=64)
    {
        dim3 grid(MROWS / 128, NP2 / 128);   // (256, 5)
        gemm_bf16_nt<<<grid, 256, SMEM_TOTAL>>>(hshi, hslo, wohi, wolo,
                                                b_out, out, FF, KP2, NKC2);
    }
}